// round 13
// baseline (speedup 1.0000x reference)
#include <cuda_runtime.h>
#include <cstdint>

// QuantizedLinear(5 -> 10, bits=2) over 4M tokens, fp32.
//
// TMA (1D cp.async.bulk) moves x/out tiles gmem<->smem off the L1 pipe.
// Tile split into two 256-token halves with independent mbarriers so compute
// on half A overlaps half B's load, and A's store issues early.
// Compute: thread-pair split (even lane: outputs 0-4, odd: 5-9; pair shares a
// token) -> 5 LDS + 5 STS per warp-pass, all conflict-free. Weights
// dequantized once per block (threads 0..9) into a padded [2][32] smem block
// and loaded as 8 broadcast LDS.128 per thread.

#define THREADS 256
#define TPB 512
#define HALF 256
#define IN_F 5
#define OUT_F 10
#define XHB (HALF * IN_F * 4)    // 5120 B per half
#define OHB (HALF * OUT_F * 4)   // 10240 B per half

__global__ __launch_bounds__(THREADS, 4)
void qlinear2bit_kernel(const float* __restrict__ x,
                        const float* __restrict__ w,
                        const float* __restrict__ bias,
                        float* __restrict__ out,
                        int n_tokens)
{
    __shared__ __align__(128) float sx[2][HALF * IN_F];    // 2 x 5 KB
    __shared__ __align__(128) float so[2][HALF * OUT_F];   // 2 x 10 KB
    __shared__ __align__(16)  float swp[2][32];            // padded w+bias
    __shared__ __align__(8)   unsigned long long mbar[2];

    const int t = threadIdx.x;
    const long long tok0 = (long long)blockIdx.x * TPB;

    bool fullH[2];
    fullH[0] = (tok0 + HALF <= (long long)n_tokens);
    fullH[1] = (tok0 + 2 * HALF <= (long long)n_tokens);

    uint32_t mb[2];
    mb[0] = (uint32_t)__cvta_generic_to_shared(&mbar[0]);
    mb[1] = (uint32_t)__cvta_generic_to_shared(&mbar[1]);

    // ---- issue TMA loads for both halves immediately ----
    if (t == 0) {
        asm volatile("mbarrier.init.shared.b64 [%0], 1;" :: "r"(mb[0]));
        asm volatile("mbarrier.init.shared.b64 [%0], 1;" :: "r"(mb[1]));
        asm volatile("fence.proxy.async.shared::cta;" ::: "memory");
        #pragma unroll
        for (int hf = 0; hf < 2; hf++) {
            if (fullH[hf]) {
                const uint32_t dst =
                    (uint32_t)__cvta_generic_to_shared(sx[hf]);
                asm volatile("mbarrier.arrive.expect_tx.shared.b64 _, [%0], %1;"
                             :: "r"(mb[hf]), "r"((uint32_t)XHB));
                asm volatile(
                    "cp.async.bulk.shared::cluster.global.mbarrier::complete_tx::bytes "
                    "[%0], [%1], %2, [%3];"
                    :: "r"(dst), "l"(x + (tok0 + hf * HALF) * IN_F),
                       "r"((uint32_t)XHB), "r"(mb[hf])
                    : "memory");
            }
        }
    }

    // ---- dequantize weights into padded smem (overlapped with TMA) ----
    if (t < OUT_F) {
        float r[IN_F];
        float m = 0.0f;
        #pragma unroll
        for (int c = 0; c < IN_F; c++) {
            r[c] = w[t * IN_F + c];
            m = fmaxf(m, fabsf(r[c]));
        }
        float scale = fmaxf(m, 1e-8f);          // qmax = 2^(bits-1)-1 = 1
        float inv = 1.0f / scale;
        const int hh = t / 5, jj = t % 5;
        #pragma unroll
        for (int c = 0; c < IN_F; c++) {
            float q = rintf(r[c] * inv);        // round-half-to-even == jnp.round
            swp[hh][jj * IN_F + c] = fminf(fmaxf(q, -2.0f), 1.0f) * scale;
        }
        swp[hh][25 + jj] = bias[t];
    } else if (t >= OUT_F && t < 14) {          // zero pads for LDS.128
        const int i = t - OUT_F;
        swp[i >> 1][30 + (i & 1)] = 0.0f;
    }

    // ---- scalar fallback loads for partial halves ----
    #pragma unroll
    for (int hf = 0; hf < 2; hf++) {
        if (!fullH[hf]) {
            const long long base = tok0 + hf * HALF;
            long long nt = (long long)n_tokens - base;
            if (nt > 0) {
                const int nf = (int)(nt * IN_F);
                for (int i = t; i < nf; i += THREADS)
                    sx[hf][i] = x[base * IN_F + i];
            }
        }
    }
    __syncthreads();    // swp ready, mbarrier inits visible

    // ---- per-thread weights: 8 broadcast LDS.128 ----
    const int p = t >> 1;       // pair/token index (0..127)
    const int h = t & 1;        // output half: rows h*5 .. h*5+4
    float wr[32];
    #pragma unroll
    for (int i = 0; i < 8; i++)
        ((float4*)wr)[i] = ((const float4*)swp[h])[i];

    // ---- process halves ----
    #pragma unroll
    for (int hf = 0; hf < 2; hf++) {
        if (fullH[hf]) {
            // wait for this half's TMA load
            uint32_t done;
            asm volatile(
                "{\n\t.reg .pred pq;\n\t"
                "mbarrier.try_wait.parity.acquire.cta.shared::cta.b64 pq, [%1], %2;\n\t"
                "selp.b32 %0, 1, 0, pq;\n\t}"
                : "=r"(done) : "r"(mb[hf]), "r"(0u) : "memory");
            if (!done) {
                asm volatile(
                    "{\n\t.reg .pred P1;\n\t"
                    "W_%=:\n\t"
                    "mbarrier.try_wait.parity.acquire.cta.shared::cta.b64 P1, [%0], %1, 0x989680;\n\t"
                    "@P1 bra.uni D_%=;\n\t"
                    "bra.uni W_%=;\n\t"
                    "D_%=:\n\t}"
                    :: "r"(mb[hf]), "r"(0u) : "memory");
            }
            // compute 256 tokens: pair shares token, 2 passes
            #pragma unroll
            for (int s = 0; s < 2; s++) {
                const int tok = p + s * 128;
                float xi[IN_F];
                #pragma unroll
                for (int c = 0; c < IN_F; c++)
                    xi[c] = sx[hf][tok * IN_F + c];       // pair-multicast, 1 wf
                #pragma unroll
                for (int j = 0; j < 5; j++) {
                    float acc = wr[25 + j];
                    #pragma unroll
                    for (int c = 0; c < IN_F; c++)
                        acc = fmaf(xi[c], wr[j * IN_F + c], acc);
                    so[hf][tok * OUT_F + h * 5 + j] = acc; // conflict-free
                }
            }
            __syncthreads();
            // TMA store of this half
            if (t == 0) {
                const uint32_t src =
                    (uint32_t)__cvta_generic_to_shared(so[hf]);
                asm volatile("fence.proxy.async.shared::cta;" ::: "memory");
                asm volatile(
                    "cp.async.bulk.global.shared::cta.bulk_group [%0], [%1], %2;"
                    :: "l"(out + (tok0 + hf * HALF) * OUT_F), "r"(src),
                       "r"((uint32_t)OHB)
                    : "memory");
                asm volatile("cp.async.bulk.commit_group;" ::: "memory");
            }
        } else {
            // partial half: guarded compute + scalar store
            const long long base = tok0 + hf * HALF;
            #pragma unroll
            for (int s = 0; s < 2; s++) {
                const int tok = p + s * 128;
                if (base + tok < (long long)n_tokens) {
                    float xi[IN_F];
                    #pragma unroll
                    for (int c = 0; c < IN_F; c++)
                        xi[c] = sx[hf][tok * IN_F + c];
                    #pragma unroll
                    for (int j = 0; j < 5; j++) {
                        float acc = wr[25 + j];
                        #pragma unroll
                        for (int c = 0; c < IN_F; c++)
                            acc = fmaf(xi[c], wr[j * IN_F + c], acc);
                        so[hf][tok * OUT_F + h * 5 + j] = acc;
                    }
                }
            }
            __syncthreads();
            long long nt = (long long)n_tokens - base;
            if (nt > 0) {
                const int nof = (int)(nt * OUT_F);
                for (int i = t; i < nof; i += THREADS)
                    out[base * OUT_F + i] = so[hf][i];
            }
        }
    }

    // keep smem alive until async bulk stores have read it
    if (t == 0) {
        asm volatile("cp.async.bulk.wait_group 0;" ::: "memory");
    }
}

extern "C" void kernel_launch(void* const* d_in, const int* in_sizes, int n_in,
                              void* d_out, int out_size)
{
    const float* x    = (const float*)d_in[0];   // [N, 5]
    const float* w    = (const float*)d_in[1];   // [10, 5]
    const float* bias = (const float*)d_in[2];   // [10]
    float* out = (float*)d_out;                  // [N, 10]

    const int n_tokens = in_sizes[0] / IN_F;
    const int grid = (n_tokens + TPB - 1) / TPB;
    qlinear2bit_kernel<<<grid, THREADS>>>(x, w, bias, out, n_tokens);
}